// round 8
// baseline (speedup 1.0000x reference)
#include <cuda_runtime.h>

#define SQ   1024   // spatial sequence length (16*64)
#define CH   64     // channels == heads (c = 1 per head)
#define NHB  128    // batch * heads
#define M    16     // Chebyshev terms
#define RAD  8.0f   // fixed Chebyshev interval [-RAD, RAD] for q

// Scratch (allocation-free rule: __device__ globals)
__device__ float g_q[NHB * SQ];
__device__ float g_kh[NHB * SQ];     // k pre-scaled by log2(e)/8
__device__ float g_v[NHB * SQ];
__device__ float g_coef[NHB * 32];   // per head: ca[16] cb[16]

typedef unsigned long long u64t;

__device__ __forceinline__ float ex2f(float x) {
    float r;
    asm("ex2.approx.ftz.f32 %0, %1;" : "=f"(r) : "f"(x));
    return r;
}
__device__ __forceinline__ u64t pack2(float lo, float hi) {
    u64t r;
    asm("mov.b64 %0, {%1, %2};" : "=l"(r) : "f"(lo), "f"(hi));
    return r;
}
__device__ __forceinline__ float2 unpack2(u64t v) {
    float2 f;
    asm("mov.b64 {%0, %1}, %2;" : "=f"(f.x), "=f"(f.y) : "l"(v));
    return f;
}
__device__ __forceinline__ u64t fma2(u64t a, u64t b, u64t c) {
    u64t d;
    asm("fma.rn.f32x2 %0, %1, %2, %3;" : "=l"(d) : "l"(a), "l"(b), "l"(c));
    return d;
}
__device__ __forceinline__ u64t mul2(u64t a, u64t b) {
    u64t d;
    asm("mul.rn.f32x2 %0, %1, %2;" : "=l"(d) : "l"(a), "l"(b));
    return d;
}

// ---------------------------------------------------------------------------
// K0: QKV projections. Block = (8-s tile, b) -> 256 blocks (2/SM, 16 warps/SM).
// Thread (o = tid>>2, sp = tid&3) produces q/k/v for head o, 2 s values.
// x tile staged once in smem; W rows via __ldg; packed f32x2 FMA.
// ---------------------------------------------------------------------------
__global__ __launch_bounds__(256) void qkv_proj(
    const float* __restrict__ x,
    const float* __restrict__ Wq, const float* __restrict__ bq,
    const float* __restrict__ Wk, const float* __restrict__ bk,
    const float* __restrict__ Wv, const float* __restrict__ bv)
{
    __shared__ float xt[CH][10];     // 8-s tile, pad 10

    const int tid = threadIdx.x;
    const int b   = blockIdx.y;
    const int s0  = blockIdx.x * 8;

    {   // stage x tile: thread (c = tid>>2, j = tid&3) loads one float2
        const int c = tid >> 2, j = tid & 3;
        float2 xv = *reinterpret_cast<const float2*>(
            x + (size_t)(b * CH + c) * SQ + s0 + 2 * j);
        xt[c][2 * j]     = xv.x;
        xt[c][2 * j + 1] = xv.y;
    }
    __syncthreads();

    const int o  = tid >> 2;
    const int sp = tid & 3;
    const float KS = 0.18033688011112042f;   // log2(e) / sqrt(64)

    u64t aq = pack2(bq[o], bq[o]);
    u64t ak = pack2(bk[o], bk[o]);
    u64t av = pack2(bv[o], bv[o]);

    const float4* wqp = reinterpret_cast<const float4*>(Wq + o * CH);
    const float4* wkp = reinterpret_cast<const float4*>(Wk + o * CH);
    const float4* wvp = reinterpret_cast<const float4*>(Wv + o * CH);

#pragma unroll
    for (int c4 = 0; c4 < CH / 4; c4++) {
        float4 wq4 = __ldg(wqp + c4);
        float4 wk4 = __ldg(wkp + c4);
        float4 wv4 = __ldg(wvp + c4);
#pragma unroll
        for (int u = 0; u < 4; u++) {
            const int c = c4 * 4 + u;
            u64t xv = *reinterpret_cast<const u64t*>(&xt[c][2 * sp]);
            aq = fma2(pack2((&wq4.x)[u], (&wq4.x)[u]), xv, aq);
            ak = fma2(pack2((&wk4.x)[u], (&wk4.x)[u]), xv, ak);
            av = fma2(pack2((&wv4.x)[u], (&wv4.x)[u]), xv, av);
        }
    }
    ak = mul2(ak, pack2(KS, KS));

    const size_t idx = (size_t)(b * CH + o) * SQ + s0 + 2 * sp;
    *reinterpret_cast<u64t*>(g_q  + idx) = aq;
    *reinterpret_cast<u64t*>(g_kh + idx) = ak;
    *reinterpret_cast<u64t*>(g_v  + idx) = av;
}

// ---------------------------------------------------------------------------
// K1: per-head Chebyshev coefficients on fixed interval [-RAD, RAD].
// Block = head, 512 threads (16 warps). Warp w evaluates node w:
//   f_w = sum_t exp2(x_w * kh_t),  g_w = sum_t v_t * exp2(x_w * kh_t)
// then DCT -> 32 coefficients per head.
// ---------------------------------------------------------------------------
__global__ __launch_bounds__(512) void head_coef()
{
    __shared__ float kh[SQ], vv[SQ];
    __shared__ float fj[M], gj[M];

    const int tid = threadIdx.x;
    const int hb  = blockIdx.x;

    float2 k2 = *reinterpret_cast<const float2*>(g_kh + (size_t)hb * SQ + 2 * tid);
    float2 v2 = *reinterpret_cast<const float2*>(g_v  + (size_t)hb * SQ + 2 * tid);
    *reinterpret_cast<float2*>(kh + 2 * tid) = k2;
    *reinterpret_cast<float2*>(vv + 2 * tid) = v2;
    __syncthreads();

    const int w = tid >> 5, l = tid & 31;
    const float PI_M = 3.14159265358979f / (float)M;
    const float xw = RAD * cosf(((float)w + 0.5f) * PI_M);

    float f0 = 0.f, g0 = 0.f;
#pragma unroll 8
    for (int t = l; t < SQ; t += 32) {
        float e0 = ex2f(xw * kh[t]);
        f0 += e0;
        g0 = fmaf(e0, vv[t], g0);
    }
#pragma unroll
    for (int d = 16; d; d >>= 1) {
        f0 += __shfl_xor_sync(0xffffffffu, f0, d);
        g0 += __shfl_xor_sync(0xffffffffu, g0, d);
    }
    if (l == 0) { fj[w] = f0; gj[w] = g0; }
    __syncthreads();

    if (tid < M) {
        float af = 0.f, ag = 0.f;
#pragma unroll
        for (int j = 0; j < M; j++) {
            float wgt = cosf((float)tid * ((float)j + 0.5f) * PI_M);
            af = fmaf(fj[j], wgt, af);
            ag = fmaf(gj[j], wgt, ag);
        }
        float scale = (tid == 0) ? (1.0f / M) : (2.0f / M);
        g_coef[hb * 32 + tid]      = af * scale;
        g_coef[hb * 32 + 16 + tid] = ag * scale;
    }
}

// ---------------------------------------------------------------------------
// K2: Clenshaw per (head, s) -> o tile in smem -> Wo GEMM (f32x2) + residual.
// Block = (8-s tile, b) -> 256 blocks. Thread (o, sp) handles 2 s values.
// ---------------------------------------------------------------------------
__global__ __launch_bounds__(256) void clenshaw_outproj(
    const float* __restrict__ x,
    const float* __restrict__ Wo, const float* __restrict__ bo,
    float* __restrict__ outp)
{
    __shared__ float ot[CH][10];        // q tile, then o tile (in place)
    __shared__ float ca[CH][17];        // pad 17 -> conflict-free broadcast
    __shared__ float cb[CH][17];

    const int tid = threadIdx.x;
    const int b   = blockIdx.y;
    const int s0  = blockIdx.x * 8;

    // stage coefficients for this batch's 64 heads (coalesced)
    for (int i = tid; i < CH * 32; i += 256) {
        float v = g_coef[b * CH * 32 + i];
        int h = i >> 5, r = i & 31;
        if (r < 16) ca[h][r] = v; else cb[h][r - 16] = v;
    }
    // stage q tile
    {
        const int c = tid >> 2, j = tid & 3;
        float2 qv = *reinterpret_cast<const float2*>(
            g_q + (size_t)(b * CH + c) * SQ + s0 + 2 * j);
        ot[c][2 * j]     = qv.x;
        ot[c][2 * j + 1] = qv.y;
    }
    __syncthreads();

    const int o  = tid >> 2;
    const int sp = tid & 3;

    // Clenshaw in place on own slot (fixed interval: u = q / RAD)
    {
        float q0 = ot[o][2 * sp], q1 = ot[o][2 * sp + 1];
        const float IR = 1.0f / RAD;
        float u0 = q0 * IR, u1 = q1 * IR;
        float t0 = 2.f * u0, t1 = 2.f * u1;
        float b10 = 0.f, b20 = 0.f, d10 = 0.f, d20 = 0.f;
        float b11 = 0.f, b21 = 0.f, d11 = 0.f, d21 = 0.f;
#pragma unroll
        for (int k = M - 1; k >= 1; k--) {
            float cak = ca[o][k], cbk = cb[o][k];
            float nb0 = fmaf(t0, b10, cak - b20); b20 = b10; b10 = nb0;
            float nd0 = fmaf(t0, d10, cbk - d20); d20 = d10; d10 = nd0;
            float nb1 = fmaf(t1, b11, cak - b21); b21 = b11; b11 = nb1;
            float nd1 = fmaf(t1, d11, cbk - d21); d21 = d11; d11 = nd1;
        }
        float ca0 = ca[o][0], cb0 = cb[o][0];
        ot[o][2 * sp]     = __fdividef(fmaf(u0, d10, cb0 - d20),
                                       fmaf(u0, b10, ca0 - b20));
        ot[o][2 * sp + 1] = __fdividef(fmaf(u1, d11, cb0 - d21),
                                       fmaf(u1, b11, ca0 - b21));
    }
    __syncthreads();

    // Wo GEMM (packed f32x2) + residual
    u64t acc = pack2(bo[o], bo[o]);
    const float4* wop = reinterpret_cast<const float4*>(Wo + o * CH);
#pragma unroll
    for (int c4 = 0; c4 < CH / 4; c4++) {
        float4 w4 = __ldg(wop + c4);
#pragma unroll
        for (int u = 0; u < 4; u++) {
            const int c = c4 * 4 + u;
            u64t xv = *reinterpret_cast<const u64t*>(&ot[c][2 * sp]);
            acc = fma2(pack2((&w4.x)[u], (&w4.x)[u]), xv, acc);
        }
    }
    const size_t idx = (size_t)(b * CH + o) * SQ + s0 + 2 * sp;
    float2 rv = *reinterpret_cast<const float2*>(x + idx);
    float2 a = unpack2(acc);
    float2 o2;
    o2.x = a.x + rv.x;
    o2.y = a.y + rv.y;
    *reinterpret_cast<float2*>(outp + idx) = o2;
}

extern "C" void kernel_launch(void* const* d_in, const int* in_sizes, int n_in,
                              void* d_out, int out_size)
{
    const float* x  = (const float*)d_in[0];
    const float* Wq = (const float*)d_in[1];
    const float* bq = (const float*)d_in[2];
    const float* Wk = (const float*)d_in[3];
    const float* bk = (const float*)d_in[4];
    const float* Wv = (const float*)d_in[5];
    const float* bv = (const float*)d_in[6];
    const float* Wo = (const float*)d_in[7];
    const float* bo = (const float*)d_in[8];
    float* out = (float*)d_out;

    dim3 grid(SQ / 8, 2);
    qkv_proj<<<grid, 256>>>(x, Wq, bq, Wk, bk, Wv, bv);
    head_coef<<<NHB, 512>>>();
    clenshaw_outproj<<<grid, 256>>>(x, Wo, bo, out);
}

// round 10
// speedup vs baseline: 1.2167x; 1.2167x over previous
#include <cuda_runtime.h>

#define SQ   1024   // spatial sequence length (16*64)
#define CH   64     // channels == heads (c = 1 per head)
#define NHB  128    // batch * heads
#define M    16     // Chebyshev terms
#define RAD  8.0f   // fixed Chebyshev interval [-RAD, RAD] for q

// Scratch (allocation-free rule: __device__ globals)
__device__ float g_q[NHB * SQ];
__device__ float g_kh[NHB * SQ];     // k pre-scaled by log2(e)/8
__device__ float g_v[NHB * SQ];
__device__ float g_coef[NHB * 32];   // per head: ca[16] cb[16]

typedef unsigned long long u64t;

__device__ __forceinline__ float ex2f(float x) {
    float r;
    asm("ex2.approx.ftz.f32 %0, %1;" : "=f"(r) : "f"(x));
    return r;
}
__device__ __forceinline__ u64t pack2(float lo, float hi) {
    u64t r;
    asm("mov.b64 %0, {%1, %2};" : "=l"(r) : "f"(lo), "f"(hi));
    return r;
}
__device__ __forceinline__ float2 unpack2(u64t v) {
    float2 f;
    asm("mov.b64 {%0, %1}, %2;" : "=f"(f.x), "=f"(f.y) : "l"(v));
    return f;
}
__device__ __forceinline__ u64t fma2(u64t a, u64t b, u64t c) {
    u64t d;
    asm("fma.rn.f32x2 %0, %1, %2, %3;" : "=l"(d) : "l"(a), "l"(b), "l"(c));
    return d;
}
__device__ __forceinline__ u64t mul2(u64t a, u64t b) {
    u64t d;
    asm("mul.rn.f32x2 %0, %1, %2;" : "=l"(d) : "l"(a), "l"(b));
    return d;
}

// ---------------------------------------------------------------------------
// K0: QKV projections. Block = (16-s tile, b), 512 threads (16 warps/SM).
// All weight LDGs issued upfront (coalesced, high MLP) into registers;
// per-matrix smem staging; all-smem compute with packed f32x2 FMA.
// Thread (o = tid>>3, sp = tid&7) produces q/k/v for head o, 2 s values.
// ---------------------------------------------------------------------------
__global__ __launch_bounds__(512) void qkv_proj(
    const float* __restrict__ x,
    const float* __restrict__ Wq, const float* __restrict__ bq,
    const float* __restrict__ Wk, const float* __restrict__ bk,
    const float* __restrict__ Wv, const float* __restrict__ bv)
{
    __shared__ float wsh[CH][68];    // one weight matrix at a time, padded
    __shared__ float xt[CH][18];     // 16-s tile, pad 18 (keeps 8B align)

    const int tid = threadIdx.x;
    const int b   = blockIdx.y;
    const int s0  = blockIdx.x * 16;

    // Upfront: issue ALL global loads (weights into regs, x tile into smem).
    float4 wq0, wq1, wk0, wk1, wv0, wv1;
    {
        const int i = tid * 8;
        wq0 = *reinterpret_cast<const float4*>(Wq + i);
        wq1 = *reinterpret_cast<const float4*>(Wq + i + 4);
        wk0 = *reinterpret_cast<const float4*>(Wk + i);
        wk1 = *reinterpret_cast<const float4*>(Wk + i + 4);
        wv0 = *reinterpret_cast<const float4*>(Wv + i);
        wv1 = *reinterpret_cast<const float4*>(Wv + i + 4);
    }
    {
        const int c = tid >> 3, j = tid & 7;
        float2 xv = *reinterpret_cast<const float2*>(
            x + (size_t)(b * CH + c) * SQ + s0 + 2 * j);
        xt[c][2 * j]     = xv.x;
        xt[c][2 * j + 1] = xv.y;
    }

    const int o  = tid >> 3;
    const int sp = tid & 7;
    const float KS = 0.18033688011112042f;   // log2(e) / sqrt(64)

    u64t aq = pack2(bq[o], bq[o]);
    u64t ak = pack2(bk[o], bk[o]);
    u64t av = pack2(bv[o], bv[o]);

    const int wr_row = tid >> 3, wr_col = (tid & 7) * 8;   // = tid*8 decomposed

#pragma unroll
    for (int m = 0; m < 3; m++) {
        __syncthreads();                      // xt ready (m=0) / prior readers done
        if (m == 0) {
            *reinterpret_cast<float4*>(&wsh[wr_row][wr_col])     = wq0;
            *reinterpret_cast<float4*>(&wsh[wr_row][wr_col + 4]) = wq1;
        } else if (m == 1) {
            *reinterpret_cast<float4*>(&wsh[wr_row][wr_col])     = wk0;
            *reinterpret_cast<float4*>(&wsh[wr_row][wr_col + 4]) = wk1;
        } else {
            *reinterpret_cast<float4*>(&wsh[wr_row][wr_col])     = wv0;
            *reinterpret_cast<float4*>(&wsh[wr_row][wr_col + 4]) = wv1;
        }
        __syncthreads();

        u64t acc = (m == 0) ? aq : (m == 1) ? ak : av;
#pragma unroll
        for (int c4 = 0; c4 < CH / 4; c4++) {
            float4 w4 = *reinterpret_cast<const float4*>(&wsh[o][c4 * 4]);
#pragma unroll
            for (int u = 0; u < 4; u++) {
                u64t xv = *reinterpret_cast<const u64t*>(&xt[c4 * 4 + u][2 * sp]);
                acc = fma2(pack2((&w4.x)[u], (&w4.x)[u]), xv, acc);
            }
        }
        if (m == 0) aq = acc; else if (m == 1) ak = acc; else av = acc;
    }
    ak = mul2(ak, pack2(KS, KS));

    const size_t idx = (size_t)(b * CH + o) * SQ + s0 + 2 * sp;
    *reinterpret_cast<u64t*>(g_q  + idx) = aq;
    *reinterpret_cast<u64t*>(g_kh + idx) = ak;
    *reinterpret_cast<u64t*>(g_v  + idx) = av;
}

// ---------------------------------------------------------------------------
// K1: per-head Chebyshev coefficients on fixed interval [-RAD, RAD].
// Block = head, 512 threads. Warp w evaluates node w; DCT -> 32 coeffs.
// ---------------------------------------------------------------------------
__global__ __launch_bounds__(512) void head_coef()
{
    __shared__ float kh[SQ], vv[SQ];
    __shared__ float fj[M], gj[M];

    const int tid = threadIdx.x;
    const int hb  = blockIdx.x;

    float2 k2 = *reinterpret_cast<const float2*>(g_kh + (size_t)hb * SQ + 2 * tid);
    float2 v2 = *reinterpret_cast<const float2*>(g_v  + (size_t)hb * SQ + 2 * tid);
    *reinterpret_cast<float2*>(kh + 2 * tid) = k2;
    *reinterpret_cast<float2*>(vv + 2 * tid) = v2;
    __syncthreads();

    const int w = tid >> 5, l = tid & 31;
    const float PI_M = 3.14159265358979f / (float)M;
    const float xw = RAD * cosf(((float)w + 0.5f) * PI_M);

    float f0 = 0.f, g0 = 0.f;
#pragma unroll 8
    for (int t = l; t < SQ; t += 32) {
        float e0 = ex2f(xw * kh[t]);
        f0 += e0;
        g0 = fmaf(e0, vv[t], g0);
    }
#pragma unroll
    for (int d = 16; d; d >>= 1) {
        f0 += __shfl_xor_sync(0xffffffffu, f0, d);
        g0 += __shfl_xor_sync(0xffffffffu, g0, d);
    }
    if (l == 0) { fj[w] = f0; gj[w] = g0; }
    __syncthreads();

    if (tid < M) {
        float af = 0.f, ag = 0.f;
#pragma unroll
        for (int j = 0; j < M; j++) {
            float wgt = cosf((float)tid * ((float)j + 0.5f) * PI_M);
            af = fmaf(fj[j], wgt, af);
            ag = fmaf(gj[j], wgt, ag);
        }
        float scale = (tid == 0) ? (1.0f / M) : (2.0f / M);
        g_coef[hb * 32 + tid]      = af * scale;
        g_coef[hb * 32 + 16 + tid] = ag * scale;
    }
}

// ---------------------------------------------------------------------------
// K2: Clenshaw -> o tile -> Wo GEMM + residual. Block = (16-s tile, b),
// 512 threads. Wo + coefficients + q tile all staged upfront (coalesced).
// ---------------------------------------------------------------------------
__global__ __launch_bounds__(512) void clenshaw_outproj(
    const float* __restrict__ x,
    const float* __restrict__ Wo, const float* __restrict__ bo,
    float* __restrict__ outp)
{
    __shared__ float wsh[CH][68];
    __shared__ float ot[CH][18];        // q tile, then o tile (in place)
    __shared__ float ca[CH][17];
    __shared__ float cb[CH][17];

    const int tid = threadIdx.x;
    const int b   = blockIdx.y;
    const int s0  = blockIdx.x * 16;

    // Upfront coalesced staging: Wo (8 floats/thread), coef (4/thread), q (2/thread)
    {
        const int i = tid * 8;
        float4 w0 = *reinterpret_cast<const float4*>(Wo + i);
        float4 w1 = *reinterpret_cast<const float4*>(Wo + i + 4);
        *reinterpret_cast<float4*>(&wsh[i >> 6][i & 63])       = w0;
        *reinterpret_cast<float4*>(&wsh[i >> 6][(i & 63) + 4]) = w1;
    }
    {
        const int i = tid * 4;
        float4 cv = *reinterpret_cast<const float4*>(g_coef + b * CH * 32 + i);
#pragma unroll
        for (int u = 0; u < 4; u++) {
            int h = (i + u) >> 5, r = (i + u) & 31;
            float v = (&cv.x)[u];
            if (r < 16) ca[h][r] = v; else cb[h][r - 16] = v;
        }
    }
    {
        const int c = tid >> 3, j = tid & 7;
        float2 qv = *reinterpret_cast<const float2*>(
            g_q + (size_t)(b * CH + c) * SQ + s0 + 2 * j);
        ot[c][2 * j]     = qv.x;
        ot[c][2 * j + 1] = qv.y;
    }
    __syncthreads();

    const int o  = tid >> 3;
    const int sp = tid & 7;

    // Clenshaw in place on own slot (fixed interval: u = q / RAD)
    {
        float q0 = ot[o][2 * sp], q1 = ot[o][2 * sp + 1];
        const float IR = 1.0f / RAD;
        float u0 = q0 * IR, u1 = q1 * IR;
        float t0 = 2.f * u0, t1 = 2.f * u1;
        float b10 = 0.f, b20 = 0.f, d10 = 0.f, d20 = 0.f;
        float b11 = 0.f, b21 = 0.f, d11 = 0.f, d21 = 0.f;
#pragma unroll
        for (int k = M - 1; k >= 1; k--) {
            float cak = ca[o][k], cbk = cb[o][k];
            float nb0 = fmaf(t0, b10, cak - b20); b20 = b10; b10 = nb0;
            float nd0 = fmaf(t0, d10, cbk - d20); d20 = d10; d10 = nd0;
            float nb1 = fmaf(t1, b11, cak - b21); b21 = b11; b11 = nb1;
            float nd1 = fmaf(t1, d11, cbk - d21); d21 = d11; d11 = nd1;
        }
        float ca0 = ca[o][0], cb0 = cb[o][0];
        ot[o][2 * sp]     = __fdividef(fmaf(u0, d10, cb0 - d20),
                                       fmaf(u0, b10, ca0 - b20));
        ot[o][2 * sp + 1] = __fdividef(fmaf(u1, d11, cb0 - d21),
                                       fmaf(u1, b11, ca0 - b21));
    }
    __syncthreads();

    // Wo GEMM (packed f32x2) + residual
    u64t acc = pack2(bo[o], bo[o]);
#pragma unroll
    for (int c4 = 0; c4 < CH / 4; c4++) {
        float4 w4 = *reinterpret_cast<const float4*>(&wsh[o][c4 * 4]);
#pragma unroll
        for (int u = 0; u < 4; u++) {
            u64t xv = *reinterpret_cast<const u64t*>(&ot[c4 * 4 + u][2 * sp]);
            acc = fma2(pack2((&w4.x)[u], (&w4.x)[u]), xv, acc);
        }
    }
    const size_t idx = (size_t)(b * CH + o) * SQ + s0 + 2 * sp;
    float2 rv = *reinterpret_cast<const float2*>(x + idx);
    float2 a = unpack2(acc);
    float2 o2;
    o2.x = a.x + rv.x;
    o2.y = a.y + rv.y;
    *reinterpret_cast<float2*>(outp + idx) = o2;
}

extern "C" void kernel_launch(void* const* d_in, const int* in_sizes, int n_in,
                              void* d_out, int out_size)
{
    const float* x  = (const float*)d_in[0];
    const float* Wq = (const float*)d_in[1];
    const float* bq = (const float*)d_in[2];
    const float* Wk = (const float*)d_in[3];
    const float* bk = (const float*)d_in[4];
    const float* Wv = (const float*)d_in[5];
    const float* bv = (const float*)d_in[6];
    const float* Wo = (const float*)d_in[7];
    const float* bo = (const float*)d_in[8];
    float* out = (float*)d_out;

    dim3 grid(SQ / 16, 2);
    qkv_proj<<<grid, 512>>>(x, Wq, bq, Wk, bk, Wv, bv);
    head_coef<<<NHB, 512>>>();
    clenshaw_outproj<<<grid, 512>>>(x, Wo, bo, out);
}